// round 2
// baseline (speedup 1.0000x reference)
#include <cuda_runtime.h>
#include <math.h>

#define NN   50000
#define FDIM 128
#define CDIM 40
#define NE   600000
#define NET  (NE + NN)

// ---------------- device scratch (no allocations allowed) ----------------
__device__ int   g_deg[NN];
__device__ float g_dinv[NN];
__device__ int   g_rowptr[NN + 1];
__device__ int   g_fill[NN];
__device__ int   g_csrc[NET];
__device__ float g_cnorm[NET];
__device__ float g_h[NN * FDIM];   // GEMM output buffer
__device__ float g_a[NN * FDIM];   // aggregated buffer (layer-1 activations)

// ---------------- graph preprocessing ----------------
__global__ void k_init() {
    int i = blockIdx.x * blockDim.x + threadIdx.x;
    if (i < NN) { g_deg[i] = 1; g_fill[i] = 0; }   // deg starts at 1 (self loop)
}

__global__ void k_hist(const int* __restrict__ ei) {
    int e = blockIdx.x * blockDim.x + threadIdx.x;
    if (e < NE) atomicAdd(&g_deg[ei[NE + e]], 1);
}

__global__ void k_dinv() {
    int i = blockIdx.x * blockDim.x + threadIdx.x;
    if (i < NN) g_dinv[i] = rsqrtf((float)g_deg[i]);
}

// single-block exclusive scan of g_deg -> g_rowptr (50001 entries)
__global__ void k_scan() {
    __shared__ int warp_sums[32];
    __shared__ int s_carry;
    int tid  = threadIdx.x;
    int lane = tid & 31;
    int wid  = tid >> 5;
    if (tid == 0) s_carry = 0;
    __syncthreads();
    for (int base = 0; base < NN; base += 1024) {
        int i = base + tid;
        int v = (i < NN) ? g_deg[i] : 0;
        int x = v;
        #pragma unroll
        for (int o = 1; o < 32; o <<= 1) {
            int y = __shfl_up_sync(0xffffffffu, x, o);
            if (lane >= o) x += y;
        }
        if (lane == 31) warp_sums[wid] = x;
        __syncthreads();
        if (wid == 0) {
            int ws = warp_sums[lane];
            #pragma unroll
            for (int o = 1; o < 32; o <<= 1) {
                int y = __shfl_up_sync(0xffffffffu, ws, o);
                if (lane >= o) ws += y;
            }
            warp_sums[lane] = ws;
        }
        __syncthreads();
        int excl = s_carry + (wid ? warp_sums[wid - 1] : 0) + x - v;
        if (i < NN) g_rowptr[i] = excl;
        __syncthreads();
        if (tid == 0) s_carry += warp_sums[31];
        __syncthreads();
    }
    if (tid == 0) g_rowptr[NN] = s_carry;
}

__global__ void k_fill(const int* __restrict__ ei) {
    int e = blockIdx.x * blockDim.x + threadIdx.x;
    if (e >= NET) return;
    int s, d;
    if (e < NE) { s = ei[e]; d = ei[NE + e]; }
    else        { s = d = e - NE; }                    // self loop
    int p = g_rowptr[d] + atomicAdd(&g_fill[d], 1);
    g_csrc[p]  = s;
    g_cnorm[p] = g_dinv[s] * g_dinv[d];
}

// ---------------- fp32 GEMM: g_h[M,128] = A[M,128] @ B[128,128] ----------------
// layer==0: A = Aext (harness input x). layer!=0: A = g_a (device scratch).
#define BM 64
#define BN 128
#define BK 16
__global__ __launch_bounds__(256) void k_gemm(const float* __restrict__ Aext,
                                              const float* __restrict__ B,
                                              int layer) {
    const float* A = (layer == 0) ? Aext : g_a;
    __shared__ float As[BK * BM];
    __shared__ float Bs[BK * BN];
    int tid  = threadIdx.x;
    int row0 = blockIdx.x * BM;
    int trow = tid >> 4;          // 0..15  -> rows trow*4..+3
    int tcol = tid & 15;          // 0..15  -> cols tcol*8..+7
    int am = tid >> 2, ak = (tid & 3) * 4;    // A-load: row am, 4 k's
    int bk = tid >> 4, bn = (tid & 15) * 8;   // B-load: row bk, 8 n's
    float acc[4][8];
    #pragma unroll
    for (int i = 0; i < 4; i++)
        #pragma unroll
        for (int j = 0; j < 8; j++) acc[i][j] = 0.f;

    for (int k0 = 0; k0 < FDIM; k0 += BK) {
        float4 av = make_float4(0.f, 0.f, 0.f, 0.f);
        int arow = row0 + am;
        if (arow < NN) av = *(const float4*)&A[arow * FDIM + k0 + ak];
        As[(ak + 0) * BM + am] = av.x;
        As[(ak + 1) * BM + am] = av.y;
        As[(ak + 2) * BM + am] = av.z;
        As[(ak + 3) * BM + am] = av.w;
        float4 b0 = *(const float4*)&B[(k0 + bk) * FDIM + bn];
        float4 b1 = *(const float4*)&B[(k0 + bk) * FDIM + bn + 4];
        *(float4*)&Bs[bk * BN + bn]     = b0;
        *(float4*)&Bs[bk * BN + bn + 4] = b1;
        __syncthreads();
        #pragma unroll
        for (int k = 0; k < BK; k++) {
            float4 a4 = *(float4*)&As[k * BM + trow * 4];
            float4 bA = *(float4*)&Bs[k * BN + tcol * 8];
            float4 bB = *(float4*)&Bs[k * BN + tcol * 8 + 4];
            float a[4] = {a4.x, a4.y, a4.z, a4.w};
            float b[8] = {bA.x, bA.y, bA.z, bA.w, bB.x, bB.y, bB.z, bB.w};
            #pragma unroll
            for (int i = 0; i < 4; i++)
                #pragma unroll
                for (int j = 0; j < 8; j++) acc[i][j] += a[i] * b[j];
        }
        __syncthreads();
    }
    #pragma unroll
    for (int i = 0; i < 4; i++) {
        int r = row0 + trow * 4 + i;
        if (r < NN) {
            *(float4*)&g_h[r * FDIM + tcol * 8]     = make_float4(acc[i][0], acc[i][1], acc[i][2], acc[i][3]);
            *(float4*)&g_h[r * FDIM + tcol * 8 + 4] = make_float4(acc[i][4], acc[i][5], acc[i][6], acc[i][7]);
        }
    }
}

// ---------------- CSR pull-aggregation: out[i] = sum_j norm * g_h[src] + bias ----------------
// outext == nullptr -> write to g_a (layer 1, with relu); else write outext.
__global__ __launch_bounds__(256) void k_agg(const float* __restrict__ bias,
                                             float* __restrict__ outext, int do_relu) {
    float* out = outext ? outext : g_a;
    int gw   = (blockIdx.x * blockDim.x + threadIdx.x) >> 5;   // warp = node
    int lane = threadIdx.x & 31;
    if (gw >= NN) return;
    int p0 = g_rowptr[gw], p1 = g_rowptr[gw + 1];
    float4 acc = make_float4(0.f, 0.f, 0.f, 0.f);
    for (int p = p0; p < p1; p++) {
        int   s = g_csrc[p];
        float w = g_cnorm[p];
        float4 v = *(const float4*)&g_h[s * FDIM + lane * 4];
        acc.x += w * v.x; acc.y += w * v.y; acc.z += w * v.z; acc.w += w * v.w;
    }
    float4 b = *(const float4*)&bias[lane * 4];
    acc.x += b.x; acc.y += b.y; acc.z += b.z; acc.w += b.w;
    if (do_relu) {
        acc.x = fmaxf(acc.x, 0.f); acc.y = fmaxf(acc.y, 0.f);
        acc.z = fmaxf(acc.z, 0.f); acc.w = fmaxf(acc.w, 0.f);
    }
    *(float4*)&out[gw * FDIM + lane * 4] = acc;
}

// ---------------- fused head: logits = X @ Wl + bl, then log_softmax ----------------
__global__ __launch_bounds__(256) void k_logits(const float* __restrict__ X,
                                                const float* __restrict__ Wl,
                                                const float* __restrict__ bl,
                                                float* __restrict__ out) {
    __shared__ float Ws[FDIM * CDIM];   // 20 KB
    __shared__ float bs[CDIM];
    for (int i = threadIdx.x; i < FDIM * CDIM; i += blockDim.x) Ws[i] = Wl[i];
    for (int i = threadIdx.x; i < CDIM; i += blockDim.x) bs[i] = bl[i];
    __syncthreads();
    int lane   = threadIdx.x & 31;
    int warp_g = (blockIdx.x * blockDim.x + threadIdx.x) >> 5;
    int nwarps = (gridDim.x * blockDim.x) >> 5;
    int j1 = lane + 32;
    for (int r = warp_g; r < NN; r += nwarps) {
        float xv[4];
        #pragma unroll
        for (int m = 0; m < 4; m++) xv[m] = X[r * FDIM + m * 32 + lane];
        float a0 = 0.f, a1 = 0.f;
        #pragma unroll
        for (int k = 0; k < FDIM; k++) {
            float xk = __shfl_sync(0xffffffffu, xv[k >> 5], k & 31);
            a0 += xk * Ws[k * CDIM + lane];
            if (j1 < CDIM) a1 += xk * Ws[k * CDIM + j1];
        }
        a0 += bs[lane];
        float l1v = (j1 < CDIM) ? (a1 + bs[j1]) : -INFINITY;
        float m = fmaxf(a0, l1v);
        #pragma unroll
        for (int o = 16; o; o >>= 1) m = fmaxf(m, __shfl_xor_sync(0xffffffffu, m, o));
        float se = expf(a0 - m) + ((j1 < CDIM) ? expf(l1v - m) : 0.f);
        #pragma unroll
        for (int o = 16; o; o >>= 1) se += __shfl_xor_sync(0xffffffffu, se, o);
        float lse = logf(se);
        out[r * CDIM + lane] = a0 - m - lse;
        if (j1 < CDIM) out[r * CDIM + j1] = l1v - m - lse;
    }
}

// ---------------- launcher (kernel launches ONLY — graph-capture safe) ----------------
extern "C" void kernel_launch(void* const* d_in, const int* in_sizes, int n_in,
                              void* d_out, int out_size) {
    const float* x  = (const float*)d_in[0];
    const int*   ei = (const int*)d_in[1];     // JAX int64 request silently yields int32
    const float* W1 = (const float*)d_in[2];
    const float* b1 = (const float*)d_in[3];
    const float* W2 = (const float*)d_in[4];
    const float* b2 = (const float*)d_in[5];
    const float* Wl = (const float*)d_in[6];
    const float* bl = (const float*)d_in[7];
    float* out  = (float*)d_out;
    float* xemb = out + (size_t)NN * CDIM;     // second output lives after logits

    // graph preprocessing (re-done every replay; deterministic up to fp sum order)
    k_init<<<(NN + 255) / 256, 256>>>();
    k_hist<<<(NE + 255) / 256, 256>>>(ei);
    k_dinv<<<(NN + 255) / 256, 256>>>();
    k_scan<<<1, 1024>>>();
    k_fill<<<(NET + 255) / 256, 256>>>(ei);

    int gemm_blocks = (NN + BM - 1) / BM;
    int agg_blocks  = (NN * 32 + 255) / 256;

    // layer 1: g_h = x @ W1 ; g_a = relu(agg(g_h) + b1)
    k_gemm<<<gemm_blocks, 256>>>(x, W1, 0);
    k_agg<<<agg_blocks, 256>>>(b1, nullptr, 1);

    // layer 2: g_h = g_a @ W2 ; x_emb = agg(g_h) + b2
    k_gemm<<<gemm_blocks, 256>>>(nullptr, W2, 1);
    k_agg<<<agg_blocks, 256>>>(b2, xemb, 0);

    // head: log_softmax(x_emb @ Wl + bl)
    k_logits<<<296, 256>>>(xemb, Wl, bl, out);
}

// round 4
// speedup vs baseline: 1.2157x; 1.2157x over previous
#include <cuda_runtime.h>
#include <math.h>

#define NN   50000
#define FDIM 128
#define CDIM 40
#define NE   600000
#define NET  (NE + NN)
#define NSCB 49               // ceil(NN/1024) scan blocks

// ---------------- device scratch (no allocations allowed) ----------------
__device__ int   g_deg[NN];
__device__ float g_dinv[NN];
__device__ int   g_rowptr[NN + 1];
__device__ int   g_fill[NN];
__device__ int   g_bsum[64];
__device__ int   g_boff[64];
__device__ int   g_csrc[NET];
__device__ float g_cnorm[NET];
__device__ float g_h[NN * FDIM];   // GEMM output buffer
__device__ float g_a[NN * FDIM];   // aggregated buffer (layer-1 activations)

// ---------------- graph preprocessing ----------------
__global__ void k_zero() {
    int i = blockIdx.x * blockDim.x + threadIdx.x;
    if (i < NN) g_deg[i] = 0;
}

__global__ void k_hist(const int* __restrict__ ei) {
    int e = blockIdx.x * blockDim.x + threadIdx.x;
    if (e < NE) atomicAdd(&g_deg[ei[NE + e]], 1);
}

// phase 1: per-block (1024-wide) exclusive scan of (deg+1); also dinv
__global__ __launch_bounds__(1024) void k_scan1() {
    __shared__ int warp_sums[32];
    int tid  = threadIdx.x;
    int lane = tid & 31;
    int wid  = tid >> 5;
    int i = blockIdx.x * 1024 + tid;
    int v = 0;
    if (i < NN) {
        v = g_deg[i] + 1;                       // +1 self loop
        g_dinv[i] = rsqrtf((float)v);
    }
    int x = v;
    #pragma unroll
    for (int o = 1; o < 32; o <<= 1) {
        int y = __shfl_up_sync(0xffffffffu, x, o);
        if (lane >= o) x += y;
    }
    if (lane == 31) warp_sums[wid] = x;
    __syncthreads();
    if (wid == 0) {
        int ws = warp_sums[lane];
        #pragma unroll
        for (int o = 1; o < 32; o <<= 1) {
            int y = __shfl_up_sync(0xffffffffu, ws, o);
            if (lane >= o) ws += y;
        }
        warp_sums[lane] = ws;
    }
    __syncthreads();
    int excl = (wid ? warp_sums[wid - 1] : 0) + x - v;
    if (i < NN) g_rowptr[i] = excl;
    if (tid == 1023) g_bsum[blockIdx.x] = excl + v;
}

// phase 2: scan the 49 block sums — ONE warp, two 32-chunks with explicit carry
__global__ void k_scan2() {
    int lane = threadIdx.x;       // 0..31, single warp
    int carry = 0;
    #pragma unroll
    for (int chunk = 0; chunk < 2; chunk++) {
        int idx = chunk * 32 + lane;
        int v = (idx < NSCB) ? g_bsum[idx] : 0;
        int x = v;
        #pragma unroll
        for (int o = 1; o < 32; o <<= 1) {
            int y = __shfl_up_sync(0xffffffffu, x, o);
            if (lane >= o) x += y;
        }
        if (idx < NSCB) g_boff[idx] = carry + x - v;
        if (idx == NSCB - 1) g_rowptr[NN] = carry + x;   // total = NET
        carry += __shfl_sync(0xffffffffu, x, 31);
    }
}

// phase 3: add block offsets; zero fill counters
__global__ __launch_bounds__(1024) void k_scan3() {
    int i = blockIdx.x * 1024 + threadIdx.x;
    if (i < NN) {
        g_rowptr[i] += g_boff[blockIdx.x];
        g_fill[i] = 0;
    }
}

__global__ void k_fill(const int* __restrict__ ei) {
    int e = blockIdx.x * blockDim.x + threadIdx.x;
    if (e >= NET) return;
    int s, d;
    if (e < NE) { s = ei[e]; d = ei[NE + e]; }
    else        { s = d = e - NE; }                    // self loop
    int p = g_rowptr[d] + atomicAdd(&g_fill[d], 1);
    g_csrc[p]  = s;
    g_cnorm[p] = g_dinv[s] * g_dinv[d];
}

// ---------------- fp32 GEMM: g_h[M,128] = A[M,128] @ B[128,128] ----------------
// 128x128 tile, BK=8, 8x8 microtile, 256 threads
#define GBM 128
#define GBK 8
__global__ __launch_bounds__(256) void k_gemm(const float* __restrict__ Aext,
                                              const float* __restrict__ B,
                                              int layer) {
    const float* A = layer ? g_a : Aext;
    __shared__ float As[GBK][GBM];
    __shared__ float Bs[GBK][GBM];
    int tid  = threadIdx.x;
    int row0 = blockIdx.x * GBM;
    int am = tid >> 1, ak = (tid & 1) * 4;     // A: row am, k's ak..ak+3
    int bk = tid >> 5, bn = (tid & 31) * 4;    // B: row bk, n's bn..bn+3
    int ty = tid >> 4, tx = tid & 15;          // 8x8 microtile at (ty*8, tx*8)
    float acc[8][8];
    #pragma unroll
    for (int i = 0; i < 8; i++)
        #pragma unroll
        for (int j = 0; j < 8; j++) acc[i][j] = 0.f;

    for (int k0 = 0; k0 < FDIM; k0 += GBK) {
        float4 av = make_float4(0.f, 0.f, 0.f, 0.f);
        int arow = row0 + am;
        if (arow < NN) av = *(const float4*)&A[arow * FDIM + k0 + ak];
        As[ak + 0][am] = av.x;
        As[ak + 1][am] = av.y;
        As[ak + 2][am] = av.z;
        As[ak + 3][am] = av.w;
        *(float4*)&Bs[bk][bn] = *(const float4*)&B[(k0 + bk) * FDIM + bn];
        __syncthreads();
        #pragma unroll
        for (int k = 0; k < GBK; k++) {
            float4 a0 = *(float4*)&As[k][ty * 8];
            float4 a1 = *(float4*)&As[k][ty * 8 + 4];
            float4 b0 = *(float4*)&Bs[k][tx * 8];
            float4 b1 = *(float4*)&Bs[k][tx * 8 + 4];
            float a[8] = {a0.x, a0.y, a0.z, a0.w, a1.x, a1.y, a1.z, a1.w};
            float b[8] = {b0.x, b0.y, b0.z, b0.w, b1.x, b1.y, b1.z, b1.w};
            #pragma unroll
            for (int i = 0; i < 8; i++)
                #pragma unroll
                for (int j = 0; j < 8; j++) acc[i][j] += a[i] * b[j];
        }
        __syncthreads();
    }
    #pragma unroll
    for (int i = 0; i < 8; i++) {
        int r = row0 + ty * 8 + i;
        if (r < NN) {
            *(float4*)&g_h[r * FDIM + tx * 8]     = make_float4(acc[i][0], acc[i][1], acc[i][2], acc[i][3]);
            *(float4*)&g_h[r * FDIM + tx * 8 + 4] = make_float4(acc[i][4], acc[i][5], acc[i][6], acc[i][7]);
        }
    }
}

// ---------------- CSR pull-aggregation: out[i] = sum_j norm * g_h[src] + bias ----------------
__global__ __launch_bounds__(256) void k_agg(const float* __restrict__ bias,
                                             float* __restrict__ outext, int do_relu) {
    float* out = outext ? outext : g_a;
    int gw   = (blockIdx.x * blockDim.x + threadIdx.x) >> 5;   // warp = node
    int lane = threadIdx.x & 31;
    if (gw >= NN) return;
    int p0 = g_rowptr[gw], p1 = g_rowptr[gw + 1];
    float4 acc = make_float4(0.f, 0.f, 0.f, 0.f);
    for (int p = p0; p < p1; p++) {
        int   s = g_csrc[p];
        float w = g_cnorm[p];
        float4 v = *(const float4*)&g_h[s * FDIM + lane * 4];
        acc.x += w * v.x; acc.y += w * v.y; acc.z += w * v.z; acc.w += w * v.w;
    }
    float4 b = *(const float4*)&bias[lane * 4];
    acc.x += b.x; acc.y += b.y; acc.z += b.z; acc.w += b.w;
    if (do_relu) {
        acc.x = fmaxf(acc.x, 0.f); acc.y = fmaxf(acc.y, 0.f);
        acc.z = fmaxf(acc.z, 0.f); acc.w = fmaxf(acc.w, 0.f);
    }
    *(float4*)&out[gw * FDIM + lane * 4] = acc;
}

// ---------------- fused head: logits = X @ Wl + bl, then log_softmax ----------------
__global__ __launch_bounds__(256) void k_logits(const float* __restrict__ X,
                                                const float* __restrict__ Wl,
                                                const float* __restrict__ bl,
                                                float* __restrict__ out) {
    __shared__ float Ws[FDIM * CDIM];   // 20 KB
    __shared__ float bs[CDIM];
    for (int i = threadIdx.x; i < FDIM * CDIM; i += blockDim.x) Ws[i] = Wl[i];
    for (int i = threadIdx.x; i < CDIM; i += blockDim.x) bs[i] = bl[i];
    __syncthreads();
    int lane   = threadIdx.x & 31;
    int warp_g = (blockIdx.x * blockDim.x + threadIdx.x) >> 5;
    int nwarps = (gridDim.x * blockDim.x) >> 5;
    int j1 = lane + 32;
    for (int r = warp_g; r < NN; r += nwarps) {
        float xv[4];
        #pragma unroll
        for (int m = 0; m < 4; m++) xv[m] = X[r * FDIM + m * 32 + lane];
        float a0 = 0.f, a1 = 0.f;
        #pragma unroll
        for (int k = 0; k < FDIM; k++) {
            float xk = __shfl_sync(0xffffffffu, xv[k >> 5], k & 31);
            a0 += xk * Ws[k * CDIM + lane];
            if (j1 < CDIM) a1 += xk * Ws[k * CDIM + j1];
        }
        a0 += bs[lane];
        float l1v = (j1 < CDIM) ? (a1 + bs[j1]) : -INFINITY;
        float m = fmaxf(a0, l1v);
        #pragma unroll
        for (int o = 16; o; o >>= 1) m = fmaxf(m, __shfl_xor_sync(0xffffffffu, m, o));
        float se = expf(a0 - m) + ((j1 < CDIM) ? expf(l1v - m) : 0.f);
        #pragma unroll
        for (int o = 16; o; o >>= 1) se += __shfl_xor_sync(0xffffffffu, se, o);
        float lse = logf(se);
        out[r * CDIM + lane] = a0 - m - lse;
        if (j1 < CDIM) out[r * CDIM + j1] = l1v - m - lse;
    }
}

// ---------------- launcher (kernel launches ONLY — graph-capture safe) ----------------
extern "C" void kernel_launch(void* const* d_in, const int* in_sizes, int n_in,
                              void* d_out, int out_size) {
    const float* x  = (const float*)d_in[0];
    const int*   ei = (const int*)d_in[1];     // JAX int64 request silently yields int32
    const float* W1 = (const float*)d_in[2];
    const float* b1 = (const float*)d_in[3];
    const float* W2 = (const float*)d_in[4];
    const float* b2 = (const float*)d_in[5];
    const float* Wl = (const float*)d_in[6];
    const float* bl = (const float*)d_in[7];
    float* out  = (float*)d_out;
    float* xemb = out + (size_t)NN * CDIM;     // second output lives after logits

    // graph preprocessing
    k_zero <<<(NN + 255) / 256, 256>>>();
    k_hist <<<(NE + 255) / 256, 256>>>(ei);
    k_scan1<<<NSCB, 1024>>>();
    k_scan2<<<1, 32>>>();
    k_scan3<<<NSCB, 1024>>>();
    k_fill <<<(NET + 255) / 256, 256>>>(ei);

    int gemm_blocks = (NN + GBM - 1) / GBM;
    int agg_blocks  = (NN * 32 + 255) / 256;

    // layer 1: g_h = x @ W1 ; g_a = relu(agg(g_h) + b1)
    k_gemm<<<gemm_blocks, 256>>>(x, W1, 0);
    k_agg<<<agg_blocks, 256>>>(b1, nullptr, 1);

    // layer 2: g_h = g_a @ W2 ; x_emb = agg(g_h) + b2
    k_gemm<<<gemm_blocks, 256>>>(nullptr, W2, 1);
    k_agg<<<agg_blocks, 256>>>(b2, xemb, 0);

    // head: log_softmax(x_emb @ Wl + bl)
    k_logits<<<296, 256>>>(xemb, Wl, bl, out);
}

// round 8
// speedup vs baseline: 1.2783x; 1.0515x over previous
#include <cuda_runtime.h>
#include <cuda_fp16.h>
#include <math.h>

#define NN   50000
#define FDIM 128
#define CDIM 40
#define NE   600000
#define NET  (NE + NN)
#define NSCB 49               // ceil(NN/1024) scan blocks

// bit-casts (no standard intrinsics exist for half2<->uint)
static __device__ __forceinline__ unsigned int h2_as_u32(__half2 h) {
    return *reinterpret_cast<unsigned int*>(&h);
}
static __device__ __forceinline__ __half2 u32_as_h2(unsigned int u) {
    return *reinterpret_cast<__half2*>(&u);
}

// ---------------- device scratch (no allocations allowed) ----------------
__device__ int     g_deg[NN];
__device__ float   g_dinv[NN];
__device__ int     g_rowptr[NN + 1];
__device__ int     g_fill[NN];
__device__ int     g_bsum[64];
__device__ int2    g_edge[NET];         // (src, norm-bits) packed
__device__ __half2 g_hh[NN * (FDIM/2)]; // GEMM output in fp16 (gather-traffic halved)
__device__ float   g_a[NN * FDIM];      // aggregated buffer (layer-1 activations)

// ---------------- graph preprocessing ----------------
__global__ void k_zero() {
    int i = blockIdx.x * blockDim.x + threadIdx.x;
    if (i < NN) g_deg[i] = 0;
}

__global__ void k_hist(const int* __restrict__ ei) {
    int e = blockIdx.x * blockDim.x + threadIdx.x;
    if (e < NE) atomicAdd(&g_deg[ei[NE + e]], 1);
}

// phase 1: per-block (1024-wide) exclusive scan of (deg+1); also dinv
__global__ __launch_bounds__(1024) void k_scan1() {
    __shared__ int warp_sums[32];
    int tid  = threadIdx.x;
    int lane = tid & 31;
    int wid  = tid >> 5;
    int i = blockIdx.x * 1024 + tid;
    int v = 0;
    if (i < NN) {
        v = g_deg[i] + 1;                       // +1 self loop
        g_dinv[i] = rsqrtf((float)v);
    }
    int x = v;
    #pragma unroll
    for (int o = 1; o < 32; o <<= 1) {
        int y = __shfl_up_sync(0xffffffffu, x, o);
        if (lane >= o) x += y;
    }
    if (lane == 31) warp_sums[wid] = x;
    __syncthreads();
    if (wid == 0) {
        int ws = warp_sums[lane];
        #pragma unroll
        for (int o = 1; o < 32; o <<= 1) {
            int y = __shfl_up_sync(0xffffffffu, ws, o);
            if (lane >= o) ws += y;
        }
        warp_sums[lane] = ws;
    }
    __syncthreads();
    int excl = (wid ? warp_sums[wid - 1] : 0) + x - v;
    if (i < NN) g_rowptr[i] = excl;
    if (tid == 1023) g_bsum[blockIdx.x] = excl + v;
}

// phase 2+3 fused: each block reduces its own prefix of block sums, adds offset,
// zeroes fill counters. rowptr[NN] is the known constant NET.
__global__ __launch_bounds__(1024) void k_scan3() {
    __shared__ int s_off;
    int b = blockIdx.x;
    if (threadIdx.x < 32) {
        int lane = threadIdx.x;
        int acc = 0;
        for (int idx = lane; idx < b; idx += 32) acc += g_bsum[idx];   // <=2 iters
        #pragma unroll
        for (int o = 16; o; o >>= 1) acc += __shfl_xor_sync(0xffffffffu, acc, o);
        if (lane == 0) s_off = acc;
    }
    __syncthreads();
    int i = b * 1024 + threadIdx.x;
    if (i < NN) {
        g_rowptr[i] += s_off;
        g_fill[i] = 0;
    }
    if (b == 0 && threadIdx.x == 0) g_rowptr[NN] = NET;
}

__global__ void k_fill(const int* __restrict__ ei) {
    int e = blockIdx.x * blockDim.x + threadIdx.x;
    if (e >= NET) return;
    int s, d;
    if (e < NE) { s = ei[e]; d = ei[NE + e]; }
    else        { s = d = e - NE; }                    // self loop
    int p = g_rowptr[d] + atomicAdd(&g_fill[d], 1);
    g_edge[p] = make_int2(s, __float_as_int(g_dinv[s] * g_dinv[d]));
}

// ---------------- fp32 GEMM: g_hh[M,128](fp16) = A[M,128] @ B[128,128] ----------------
// 128x128 tile, BK=8, 8x8 microtile, 256 threads; fp32 accumulate, fp16 store
#define GBM 128
#define GBK 8
__global__ __launch_bounds__(256) void k_gemm(const float* __restrict__ Aext,
                                              const float* __restrict__ B,
                                              int layer) {
    const float* A = layer ? g_a : Aext;
    __shared__ float As[GBK][GBM];
    __shared__ float Bs[GBK][GBM];
    int tid  = threadIdx.x;
    int row0 = blockIdx.x * GBM;
    int am = tid >> 1, ak = (tid & 1) * 4;     // A: row am, k's ak..ak+3
    int bk = tid >> 5, bn = (tid & 31) * 4;    // B: row bk, n's bn..bn+3
    int ty = tid >> 4, tx = tid & 15;          // 8x8 microtile at (ty*8, tx*8)
    float acc[8][8];
    #pragma unroll
    for (int i = 0; i < 8; i++)
        #pragma unroll
        for (int j = 0; j < 8; j++) acc[i][j] = 0.f;

    for (int k0 = 0; k0 < FDIM; k0 += GBK) {
        float4 av = make_float4(0.f, 0.f, 0.f, 0.f);
        int arow = row0 + am;
        if (arow < NN) av = *(const float4*)&A[arow * FDIM + k0 + ak];
        As[ak + 0][am] = av.x;
        As[ak + 1][am] = av.y;
        As[ak + 2][am] = av.z;
        As[ak + 3][am] = av.w;
        *(float4*)&Bs[bk][bn] = *(const float4*)&B[(k0 + bk) * FDIM + bn];
        __syncthreads();
        #pragma unroll
        for (int k = 0; k < GBK; k++) {
            float4 a0 = *(float4*)&As[k][ty * 8];
            float4 a1 = *(float4*)&As[k][ty * 8 + 4];
            float4 b0 = *(float4*)&Bs[k][tx * 8];
            float4 b1 = *(float4*)&Bs[k][tx * 8 + 4];
            float a[8] = {a0.x, a0.y, a0.z, a0.w, a1.x, a1.y, a1.z, a1.w};
            float b[8] = {b0.x, b0.y, b0.z, b0.w, b1.x, b1.y, b1.z, b1.w};
            #pragma unroll
            for (int i = 0; i < 8; i++)
                #pragma unroll
                for (int j = 0; j < 8; j++) acc[i][j] += a[i] * b[j];
        }
        __syncthreads();
    }
    // epilogue: fp32 -> half2 x4 -> one 16B store per row-chunk
    #pragma unroll
    for (int i = 0; i < 8; i++) {
        int r = row0 + ty * 8 + i;
        if (r < NN) {
            uint4 pkt;
            pkt.x = h2_as_u32(__floats2half2_rn(acc[i][0], acc[i][1]));
            pkt.y = h2_as_u32(__floats2half2_rn(acc[i][2], acc[i][3]));
            pkt.z = h2_as_u32(__floats2half2_rn(acc[i][4], acc[i][5]));
            pkt.w = h2_as_u32(__floats2half2_rn(acc[i][6], acc[i][7]));
            ((uint4*)&g_hh[r * (FDIM/2)])[tx] = pkt;
        }
    }
}

// ---------------- CSR pull-aggregation: out[i] = sum_j norm * g_hh[src] + bias ----------------
__global__ __launch_bounds__(256) void k_agg(const float* __restrict__ bias,
                                             float* __restrict__ outext, int do_relu) {
    float* out = outext ? outext : g_a;
    int gw   = (blockIdx.x * blockDim.x + threadIdx.x) >> 5;   // warp = node
    int lane = threadIdx.x & 31;
    if (gw >= NN) return;
    int p0 = g_rowptr[gw], p1 = g_rowptr[gw + 1];
    float4 acc = make_float4(0.f, 0.f, 0.f, 0.f);
    const uint2* hh = (const uint2*)g_hh;          // 8B = 4 halves; row = 32 uint2
    for (int p = p0; p < p1; p++) {
        int2  e = g_edge[p];
        int   s = e.x;
        float w = __int_as_float(e.y);
        uint2 v = hh[s * 32 + lane];
        float2 f0 = __half22float2(u32_as_h2(v.x));
        float2 f1 = __half22float2(u32_as_h2(v.y));
        acc.x += w * f0.x; acc.y += w * f0.y;
        acc.z += w * f1.x; acc.w += w * f1.y;
    }
    float4 b = *(const float4*)&bias[lane * 4];
    acc.x += b.x; acc.y += b.y; acc.z += b.z; acc.w += b.w;
    if (do_relu) {
        acc.x = fmaxf(acc.x, 0.f); acc.y = fmaxf(acc.y, 0.f);
        acc.z = fmaxf(acc.z, 0.f); acc.w = fmaxf(acc.w, 0.f);
    }
    *(float4*)&out[gw * FDIM + lane * 4] = acc;
}

// ---------------- fused head: logits = X @ Wl + bl, then log_softmax ----------------
__global__ __launch_bounds__(256) void k_logits(const float* __restrict__ X,
                                                const float* __restrict__ Wl,
                                                const float* __restrict__ bl,
                                                float* __restrict__ out) {
    __shared__ float Ws[FDIM * CDIM];   // 20 KB
    __shared__ float bs[CDIM];
    for (int i = threadIdx.x; i < FDIM * CDIM; i += blockDim.x) Ws[i] = Wl[i];
    for (int i = threadIdx.x; i < CDIM; i += blockDim.x) bs[i] = bl[i];
    __syncthreads();
    int lane   = threadIdx.x & 31;
    int warp_g = (blockIdx.x * blockDim.x + threadIdx.x) >> 5;
    int nwarps = (gridDim.x * blockDim.x) >> 5;
    int j1 = lane + 32;
    for (int r = warp_g; r < NN; r += nwarps) {
        float xv[4];
        #pragma unroll
        for (int m = 0; m < 4; m++) xv[m] = X[r * FDIM + m * 32 + lane];
        float a0 = 0.f, a1 = 0.f;
        #pragma unroll
        for (int k = 0; k < FDIM; k++) {
            float xk = __shfl_sync(0xffffffffu, xv[k >> 5], k & 31);
            a0 += xk * Ws[k * CDIM + lane];
            if (j1 < CDIM) a1 += xk * Ws[k * CDIM + j1];
        }
        a0 += bs[lane];
        float l1v = (j1 < CDIM) ? (a1 + bs[j1]) : -INFINITY;
        float m = fmaxf(a0, l1v);
        #pragma unroll
        for (int o = 16; o; o >>= 1) m = fmaxf(m, __shfl_xor_sync(0xffffffffu, m, o));
        float se = expf(a0 - m) + ((j1 < CDIM) ? expf(l1v - m) : 0.f);
        #pragma unroll
        for (int o = 16; o; o >>= 1) se += __shfl_xor_sync(0xffffffffu, se, o);
        float lse = logf(se);
        out[r * CDIM + lane] = a0 - m - lse;
        if (j1 < CDIM) out[r * CDIM + j1] = l1v - m - lse;
    }
}

// ---------------- launcher (kernel launches ONLY — graph-capture safe) ----------------
extern "C" void kernel_launch(void* const* d_in, const int* in_sizes, int n_in,
                              void* d_out, int out_size) {
    const float* x  = (const float*)d_in[0];
    const int*   ei = (const int*)d_in[1];     // JAX int64 request silently yields int32
    const float* W1 = (const float*)d_in[2];
    const float* b1 = (const float*)d_in[3];
    const float* W2 = (const float*)d_in[4];
    const float* b2 = (const float*)d_in[5];
    const float* Wl = (const float*)d_in[6];
    const float* bl = (const float*)d_in[7];
    float* out  = (float*)d_out;
    float* xemb = out + (size_t)NN * CDIM;     // second output lives after logits

    // graph preprocessing
    k_zero <<<(NN + 255) / 256, 256>>>();
    k_hist <<<(NE + 255) / 256, 256>>>(ei);
    k_scan1<<<NSCB, 1024>>>();
    k_scan3<<<NSCB, 1024>>>();
    k_fill <<<(NET + 255) / 256, 256>>>(ei);

    int gemm_blocks = (NN + GBM - 1) / GBM;
    int agg_blocks  = (NN * 32 + 255) / 256;

    // layer 1: g_hh = fp16(x @ W1) ; g_a = relu(agg(g_hh) + b1)
    k_gemm<<<gemm_blocks, 256>>>(x, W1, 0);
    k_agg<<<agg_blocks, 256>>>(b1, nullptr, 1);

    // layer 2: g_hh = fp16(g_a @ W2) ; x_emb = agg(g_hh) + b2
    k_gemm<<<gemm_blocks, 256>>>(nullptr, W2, 1);
    k_agg<<<agg_blocks, 256>>>(b2, xemb, 0);

    // head: log_softmax(x_emb @ Wl + bl)
    k_logits<<<296, 256>>>(xemb, Wl, bl, out);
}

// round 11
// speedup vs baseline: 1.7568x; 1.3743x over previous
#include <cuda_runtime.h>
#include <cuda_fp16.h>
#include <math.h>
#include <stdint.h>

#define NN   50000
#define FDIM 128
#define CDIM 40
#define NE   600000
#define NET  (NE + NN)
#define NSCB 49               // ceil(NN/1024) scan blocks

// bit-casts (no standard intrinsics exist for half2<->uint)
static __device__ __forceinline__ unsigned int h2_as_u32(__half2 h) {
    return *reinterpret_cast<unsigned int*>(&h);
}
static __device__ __forceinline__ __half2 u32_as_h2(unsigned int u) {
    return *reinterpret_cast<__half2*>(&u);
}

// ---------------- device scratch (no allocations allowed) ----------------
__device__ int     g_deg[NN];
__device__ float   g_dinv[NN];
__device__ int     g_rowptr[NN + 1];
__device__ int     g_fill[NN];
__device__ int     g_bsum[64];
__device__ int2    g_edge[NET];         // (src, norm-bits) packed
__device__ __half2 g_hh[NN * (FDIM/2)]; // GEMM output in fp16 (gather-traffic halved)
__device__ float   g_a[NN * FDIM];      // aggregated buffer (layer-1 activations)

// ---------------- graph preprocessing ----------------
__global__ void k_zero() {
    int i = blockIdx.x * blockDim.x + threadIdx.x;
    if (i < NN) g_deg[i] = 0;
}

__global__ void k_hist(const int* __restrict__ ei) {
    int e = blockIdx.x * blockDim.x + threadIdx.x;
    if (e < NE) atomicAdd(&g_deg[ei[NE + e]], 1);
}

// phase 1: per-block (1024-wide) exclusive scan of (deg+1); also dinv
__global__ __launch_bounds__(1024) void k_scan1() {
    __shared__ int warp_sums[32];
    int tid  = threadIdx.x;
    int lane = tid & 31;
    int wid  = tid >> 5;
    int i = blockIdx.x * 1024 + tid;
    int v = 0;
    if (i < NN) {
        v = g_deg[i] + 1;                       // +1 self loop
        g_dinv[i] = rsqrtf((float)v);
    }
    int x = v;
    #pragma unroll
    for (int o = 1; o < 32; o <<= 1) {
        int y = __shfl_up_sync(0xffffffffu, x, o);
        if (lane >= o) x += y;
    }
    if (lane == 31) warp_sums[wid] = x;
    __syncthreads();
    if (wid == 0) {
        int ws = warp_sums[lane];
        #pragma unroll
        for (int o = 1; o < 32; o <<= 1) {
            int y = __shfl_up_sync(0xffffffffu, ws, o);
            if (lane >= o) ws += y;
        }
        warp_sums[lane] = ws;
    }
    __syncthreads();
    int excl = (wid ? warp_sums[wid - 1] : 0) + x - v;
    if (i < NN) g_rowptr[i] = excl;
    if (tid == 1023) g_bsum[blockIdx.x] = excl + v;
}

// phase 2+3 fused: each block reduces its own prefix of block sums, adds offset,
// zeroes fill counters. rowptr[NN] is the known constant NET.
__global__ __launch_bounds__(1024) void k_scan3() {
    __shared__ int s_off;
    int b = blockIdx.x;
    if (threadIdx.x < 32) {
        int lane = threadIdx.x;
        int acc = 0;
        for (int idx = lane; idx < b; idx += 32) acc += g_bsum[idx];   // <=2 iters
        #pragma unroll
        for (int o = 16; o; o >>= 1) acc += __shfl_xor_sync(0xffffffffu, acc, o);
        if (lane == 0) s_off = acc;
    }
    __syncthreads();
    int i = b * 1024 + threadIdx.x;
    if (i < NN) {
        g_rowptr[i] += s_off;
        g_fill[i] = 0;
    }
    if (b == 0 && threadIdx.x == 0) g_rowptr[NN] = NET;
}

__global__ void k_fill(const int* __restrict__ ei) {
    int e = blockIdx.x * blockDim.x + threadIdx.x;
    if (e >= NET) return;
    int s, d;
    if (e < NE) { s = ei[e]; d = ei[NE + e]; }
    else        { s = d = e - NE; }                    // self loop
    int p = g_rowptr[d] + atomicAdd(&g_fill[d], 1);
    g_edge[p] = make_int2(s, __float_as_int(g_dinv[s] * g_dinv[d]));
}

// ================= HMMA GEMM: g_hh[M,128](fp16) = fp16(A[M,128]) @ fp16(W[128,128]) =================
// mma.sync.m16n8k16 (sm_80+ PTX; works on compute_103 target — tcgen05 does NOT).
// Per CTA 128 rows. SMEM (half-element indices!): A at [0, 128*LDH), BT at [128*LDH, 2*128*LDH).
// BT[n][k] = W[k][n]. 8 warps in 4x2 grid; warp tile 32x64 = 2x8 m16n8 accums; 8 K16-steps.

#define LDH 136                        // row stride in halves (16B-aligned, conflict-free)
#define SM_Ah 0                        // half-index of A tile
#define SM_Bh (128 * LDH)              // half-index of BT tile (= 17408)
#define SMEM_TC (2 * 128 * LDH * 2)    // TOTAL BYTES = 69,632
#define GT_BLOCKS ((NN + 127) / 128)

__device__ __forceinline__ uint32_t smem_u32(const void* p) {
    uint32_t a;
    asm("{ .reg .u64 t; cvta.to.shared.u64 t, %1; cvt.u32.u64 %0, t; }" : "=r"(a) : "l"(p));
    return a;
}

__device__ __forceinline__ void ldmx4(uint32_t& r0, uint32_t& r1, uint32_t& r2, uint32_t& r3,
                                      uint32_t addr) {
    asm volatile("ldmatrix.sync.aligned.m8n8.x4.shared.b16 {%0,%1,%2,%3}, [%4];"
                 : "=r"(r0), "=r"(r1), "=r"(r2), "=r"(r3) : "r"(addr));
}
__device__ __forceinline__ void ldmx2(uint32_t& r0, uint32_t& r1, uint32_t addr) {
    asm volatile("ldmatrix.sync.aligned.m8n8.x2.shared.b16 {%0,%1}, [%2];"
                 : "=r"(r0), "=r"(r1) : "r"(addr));
}
__device__ __forceinline__ void mma16816(float* c, uint32_t a0, uint32_t a1, uint32_t a2,
                                         uint32_t a3, uint32_t b0, uint32_t b1) {
    asm volatile(
        "mma.sync.aligned.m16n8k16.row.col.f32.f16.f16.f32 "
        "{%0,%1,%2,%3}, {%4,%5,%6,%7}, {%8,%9}, {%0,%1,%2,%3};"
        : "+f"(c[0]), "+f"(c[1]), "+f"(c[2]), "+f"(c[3])
        : "r"(a0), "r"(a1), "r"(a2), "r"(a3), "r"(b0), "r"(b1));
}

__global__ __launch_bounds__(256) void k_gemm_tc(const float* __restrict__ Aext,
                                                 const float* __restrict__ W, int layer) {
    extern __shared__ __half smem[];
    const float* A = layer ? g_a : Aext;
    int tid  = threadIdx.x;
    int wid  = tid >> 5;
    int lane = tid & 31;
    int row0 = blockIdx.x * 128;

    // ---- load A tile: 128 rows x 128 cols fp32 -> fp16, row stride LDH halves ----
    #pragma unroll
    for (int it = 0; it < 8; it++) {
        int i   = tid + it * 256;        // 2048 chunks of 8 halves
        int row = i >> 4;
        int cc  = (i & 15) * 8;
        float4 v0 = make_float4(0.f, 0.f, 0.f, 0.f), v1 = v0;
        int r = row0 + row;
        if (r < NN) {
            v0 = *(const float4*)&A[r * FDIM + cc];
            v1 = *(const float4*)&A[r * FDIM + cc + 4];
        }
        uint4 pk;
        pk.x = h2_as_u32(__floats2half2_rn(v0.x, v0.y));
        pk.y = h2_as_u32(__floats2half2_rn(v0.z, v0.w));
        pk.z = h2_as_u32(__floats2half2_rn(v1.x, v1.y));
        pk.w = h2_as_u32(__floats2half2_rn(v1.z, v1.w));
        *(uint4*)&smem[SM_Ah + row * LDH + cc] = pk;
    }
    // ---- load BT[n][k] = W[k][n] (coalesced over n for each k) ----
    {
        int n  = tid & 127;
        int k0 = (tid >> 7) * 64;
        #pragma unroll 8
        for (int kk = 0; kk < 64; kk++) {
            int k = k0 + kk;
            smem[SM_Bh + n * LDH + k] = __float2half_rn(W[k * FDIM + n]);
        }
    }
    __syncthreads();

    uint32_t sbA = smem_u32(&smem[SM_Ah]);
    uint32_t sbB = smem_u32(&smem[SM_Bh]);

    int m0 = (wid >> 1) * 32;
    int n0 = (wid & 1) * 64;

    float c[2][8][4];
    #pragma unroll
    for (int mi = 0; mi < 2; mi++)
        #pragma unroll
        for (int nj = 0; nj < 8; nj++)
            #pragma unroll
            for (int q = 0; q < 4; q++) c[mi][nj][q] = 0.f;

    // lane-dependent ldmatrix address components (canonical m16n8k16 patterns)
    int a_row = lane & 15;                            // rows 0..15 within 16-row tile
    int a_kof = (lane >> 4) * 8;                      // 0 or 8
    int b_row = lane & 7;                             // BT row within 8-row tile
    int b_kof = ((lane >> 3) & 1) * 8;                // 0 or 8 (x2 uses lanes 0-15)

    #pragma unroll
    for (int ks = 0; ks < 8; ks++) {
        int k0 = ks * 16;
        uint32_t a[2][4];
        #pragma unroll
        for (int mi = 0; mi < 2; mi++) {
            uint32_t addr = sbA + (uint32_t)((m0 + mi * 16 + a_row) * LDH + k0 + a_kof) * 2;
            ldmx4(a[mi][0], a[mi][1], a[mi][2], a[mi][3], addr);
        }
        uint32_t b[8][2];
        #pragma unroll
        for (int nj = 0; nj < 8; nj++) {
            uint32_t addr = sbB + (uint32_t)((n0 + nj * 8 + b_row) * LDH + k0 + b_kof) * 2;
            ldmx2(b[nj][0], b[nj][1], addr);
        }
        #pragma unroll
        for (int mi = 0; mi < 2; mi++)
            #pragma unroll
            for (int nj = 0; nj < 8; nj++)
                mma16816(c[mi][nj], a[mi][0], a[mi][1], a[mi][2], a[mi][3],
                         b[nj][0], b[nj][1]);
    }

    // ---- epilogue: fp32 accums -> half2 -> g_hh ----
    int tr = lane >> 2;            // 0..7
    int tc = (lane & 3) * 2;       // 0,2,4,6
    #pragma unroll
    for (int mi = 0; mi < 2; mi++) {
        #pragma unroll
        for (int nj = 0; nj < 8; nj++) {
            int col = n0 + nj * 8 + tc;            // even
            int r0g = row0 + m0 + mi * 16 + tr;
            int r1g = r0g + 8;
            if (r0g < NN)
                g_hh[r0g * (FDIM/2) + (col >> 1)] = __floats2half2_rn(c[mi][nj][0], c[mi][nj][1]);
            if (r1g < NN)
                g_hh[r1g * (FDIM/2) + (col >> 1)] = __floats2half2_rn(c[mi][nj][2], c[mi][nj][3]);
        }
    }
}

// ---------------- CSR pull-aggregation: out[i] = sum_j norm * g_hh[src] + bias ----------------
__global__ __launch_bounds__(256) void k_agg(const float* __restrict__ bias,
                                             float* __restrict__ outext, int do_relu) {
    float* out = outext ? outext : g_a;
    int gw   = (blockIdx.x * blockDim.x + threadIdx.x) >> 5;   // warp = node
    int lane = threadIdx.x & 31;
    if (gw >= NN) return;
    int p0 = g_rowptr[gw], p1 = g_rowptr[gw + 1];
    float4 acc = make_float4(0.f, 0.f, 0.f, 0.f);
    const uint2* hh = (const uint2*)g_hh;          // 8B = 4 halves; row = 32 uint2
    for (int p = p0; p < p1; p++) {
        int2  e = g_edge[p];
        int   s = e.x;
        float w = __int_as_float(e.y);
        uint2 v = hh[s * 32 + lane];
        float2 f0 = __half22float2(u32_as_h2(v.x));
        float2 f1 = __half22float2(u32_as_h2(v.y));
        acc.x += w * f0.x; acc.y += w * f0.y;
        acc.z += w * f1.x; acc.w += w * f1.y;
    }
    float4 b = *(const float4*)&bias[lane * 4];
    acc.x += b.x; acc.y += b.y; acc.z += b.z; acc.w += b.w;
    if (do_relu) {
        acc.x = fmaxf(acc.x, 0.f); acc.y = fmaxf(acc.y, 0.f);
        acc.z = fmaxf(acc.z, 0.f); acc.w = fmaxf(acc.w, 0.f);
    }
    *(float4*)&out[gw * FDIM + lane * 4] = acc;
}

// ---------------- fused head: logits = X @ Wl + bl, then log_softmax ----------------
__global__ __launch_bounds__(256) void k_logits(const float* __restrict__ X,
                                                const float* __restrict__ Wl,
                                                const float* __restrict__ bl,
                                                float* __restrict__ out) {
    __shared__ float Ws[FDIM * CDIM];   // 20 KB
    __shared__ float bs[CDIM];
    for (int i = threadIdx.x; i < FDIM * CDIM; i += blockDim.x) Ws[i] = Wl[i];
    for (int i = threadIdx.x; i < CDIM; i += blockDim.x) bs[i] = bl[i];
    __syncthreads();
    int lane   = threadIdx.x & 31;
    int warp_g = (blockIdx.x * blockDim.x + threadIdx.x) >> 5;
    int nwarps = (gridDim.x * blockDim.x) >> 5;
    int j1 = lane + 32;
    for (int r = warp_g; r < NN; r += nwarps) {
        float xv[4];
        #pragma unroll
        for (int m = 0; m < 4; m++) xv[m] = X[r * FDIM + m * 32 + lane];
        float a0 = 0.f, a1 = 0.f;
        #pragma unroll
        for (int k = 0; k < FDIM; k++) {
            float xk = __shfl_sync(0xffffffffu, xv[k >> 5], k & 31);
            a0 += xk * Ws[k * CDIM + lane];
            if (j1 < CDIM) a1 += xk * Ws[k * CDIM + j1];
        }
        a0 += bs[lane];
        float l1v = (j1 < CDIM) ? (a1 + bs[j1]) : -INFINITY;
        float m = fmaxf(a0, l1v);
        #pragma unroll
        for (int o = 16; o; o >>= 1) m = fmaxf(m, __shfl_xor_sync(0xffffffffu, m, o));
        float se = expf(a0 - m) + ((j1 < CDIM) ? expf(l1v - m) : 0.f);
        #pragma unroll
        for (int o = 16; o; o >>= 1) se += __shfl_xor_sync(0xffffffffu, se, o);
        float lse = logf(se);
        out[r * CDIM + lane] = a0 - m - lse;
        if (j1 < CDIM) out[r * CDIM + j1] = l1v - m - lse;
    }
}

// ---------------- launcher (kernel launches ONLY — graph-capture safe) ----------------
extern "C" void kernel_launch(void* const* d_in, const int* in_sizes, int n_in,
                              void* d_out, int out_size) {
    const float* x  = (const float*)d_in[0];
    const int*   ei = (const int*)d_in[1];     // JAX int64 request silently yields int32
    const float* W1 = (const float*)d_in[2];
    const float* b1 = (const float*)d_in[3];
    const float* W2 = (const float*)d_in[4];
    const float* b2 = (const float*)d_in[5];
    const float* Wl = (const float*)d_in[6];
    const float* bl = (const float*)d_in[7];
    float* out  = (float*)d_out;
    float* xemb = out + (size_t)NN * CDIM;     // second output lives after logits

    cudaFuncSetAttribute(k_gemm_tc, cudaFuncAttributeMaxDynamicSharedMemorySize, SMEM_TC);

    // graph preprocessing
    k_zero <<<(NN + 255) / 256, 256>>>();
    k_hist <<<(NE + 255) / 256, 256>>>(ei);
    k_scan1<<<NSCB, 1024>>>();
    k_scan3<<<NSCB, 1024>>>();
    k_fill <<<(NET + 255) / 256, 256>>>(ei);

    int agg_blocks = (NN * 32 + 255) / 256;

    // layer 1: g_hh = fp16(x @ W1) ; g_a = relu(agg(g_hh) + b1)
    k_gemm_tc<<<GT_BLOCKS, 256, SMEM_TC>>>(x, W1, 0);
    k_agg<<<agg_blocks, 256>>>(b1, nullptr, 1);

    // layer 2: g_hh = fp16(g_a @ W2) ; x_emb = agg(g_hh) + b2
    k_gemm_tc<<<GT_BLOCKS, 256, SMEM_TC>>>(nullptr, W2, 1);
    k_agg<<<agg_blocks, 256>>>(b2, xemb, 0);

    // head: log_softmax(x_emb @ Wl + bl)
    k_logits<<<296, 256>>>(xemb, Wl, bl, out);
}

// round 13
// speedup vs baseline: 2.5034x; 1.4250x over previous
#include <cuda_runtime.h>
#include <cuda_fp16.h>
#include <math.h>
#include <stdint.h>

#define NN   50000
#define FDIM 128
#define CDIM 40
#define NE   600000
#define NET  (NE + NN)
#define NSCB 49               // ceil(NN/1024) scan blocks

// bit-casts (no standard intrinsics exist for half2<->uint)
static __device__ __forceinline__ unsigned int h2_as_u32(__half2 h) {
    return *reinterpret_cast<unsigned int*>(&h);
}
static __device__ __forceinline__ __half2 u32_as_h2(unsigned int u) {
    return *reinterpret_cast<__half2*>(&u);
}

// ---------------- device scratch (no allocations allowed) ----------------
__device__ int     g_deg[NN];
__device__ float   g_dinv[NN];
__device__ int     g_rowptr[NN + 1];
__device__ int     g_fill[NN];
__device__ int     g_bsum[64];
__device__ int2    g_edge[NET];         // (src, norm-bits) packed
__device__ __half2 g_hh[NN * (FDIM/2)]; // GEMM output in fp16 (gather-traffic halved)
__device__ float   g_a[NN * FDIM];      // aggregated buffer (layer-1 activations)

// ---------------- graph preprocessing ----------------
__global__ void k_zero() {
    int i = blockIdx.x * blockDim.x + threadIdx.x;
    if (i < NN) g_deg[i] = 0;
}

__global__ void k_hist(const int* __restrict__ ei) {
    int e = blockIdx.x * blockDim.x + threadIdx.x;
    if (e < NE) atomicAdd(&g_deg[ei[NE + e]], 1);
}

// phase 1: per-block (1024-wide) exclusive scan of (deg+1); also dinv
__global__ __launch_bounds__(1024) void k_scan1() {
    __shared__ int warp_sums[32];
    int tid  = threadIdx.x;
    int lane = tid & 31;
    int wid  = tid >> 5;
    int i = blockIdx.x * 1024 + tid;
    int v = 0;
    if (i < NN) {
        v = g_deg[i] + 1;                       // +1 self loop
        g_dinv[i] = rsqrtf((float)v);
    }
    int x = v;
    #pragma unroll
    for (int o = 1; o < 32; o <<= 1) {
        int y = __shfl_up_sync(0xffffffffu, x, o);
        if (lane >= o) x += y;
    }
    if (lane == 31) warp_sums[wid] = x;
    __syncthreads();
    if (wid == 0) {
        int ws = warp_sums[lane];
        #pragma unroll
        for (int o = 1; o < 32; o <<= 1) {
            int y = __shfl_up_sync(0xffffffffu, ws, o);
            if (lane >= o) ws += y;
        }
        warp_sums[lane] = ws;
    }
    __syncthreads();
    int excl = (wid ? warp_sums[wid - 1] : 0) + x - v;
    if (i < NN) g_rowptr[i] = excl;
    if (tid == 1023) g_bsum[blockIdx.x] = excl + v;
}

// phase 2+3 fused: each block reduces its own prefix of block sums, adds offset,
// zeroes fill counters. rowptr[NN] is the known constant NET.
__global__ __launch_bounds__(1024) void k_scan3() {
    __shared__ int s_off;
    int b = blockIdx.x;
    if (threadIdx.x < 32) {
        int lane = threadIdx.x;
        int acc = 0;
        for (int idx = lane; idx < b; idx += 32) acc += g_bsum[idx];   // <=2 iters
        #pragma unroll
        for (int o = 16; o; o >>= 1) acc += __shfl_xor_sync(0xffffffffu, acc, o);
        if (lane == 0) s_off = acc;
    }
    __syncthreads();
    int i = b * 1024 + threadIdx.x;
    if (i < NN) {
        g_rowptr[i] += s_off;
        g_fill[i] = 0;
    }
    if (b == 0 && threadIdx.x == 0) g_rowptr[NN] = NET;
}

__global__ void k_fill(const int* __restrict__ ei) {
    int e = blockIdx.x * blockDim.x + threadIdx.x;
    if (e >= NET) return;
    int s, d;
    if (e < NE) { s = ei[e]; d = ei[NE + e]; }
    else        { s = d = e - NE; }                    // self loop
    int p = g_rowptr[d] + atomicAdd(&g_fill[d], 1);
    g_edge[p] = make_int2(s, __float_as_int(g_dinv[s] * g_dinv[d]));
}

// ================= shared HMMA plumbing (sm_80+ PTX; valid on compute_103) =================
#define LDH 136                        // row stride in halves (16B-aligned, conflict-free)
#define GT_BLOCKS ((NN + 127) / 128)

__device__ __forceinline__ uint32_t smem_u32(const void* p) {
    uint32_t a;
    asm("{ .reg .u64 t; cvta.to.shared.u64 t, %1; cvt.u32.u64 %0, t; }" : "=r"(a) : "l"(p));
    return a;
}
__device__ __forceinline__ void ldmx4(uint32_t& r0, uint32_t& r1, uint32_t& r2, uint32_t& r3,
                                      uint32_t addr) {
    asm volatile("ldmatrix.sync.aligned.m8n8.x4.shared.b16 {%0,%1,%2,%3}, [%4];"
                 : "=r"(r0), "=r"(r1), "=r"(r2), "=r"(r3) : "r"(addr));
}
__device__ __forceinline__ void ldmx2(uint32_t& r0, uint32_t& r1, uint32_t addr) {
    asm volatile("ldmatrix.sync.aligned.m8n8.x2.shared.b16 {%0,%1}, [%2];"
                 : "=r"(r0), "=r"(r1) : "r"(addr));
}
__device__ __forceinline__ void mma16816(float* c, uint32_t a0, uint32_t a1, uint32_t a2,
                                         uint32_t a3, uint32_t b0, uint32_t b1) {
    asm volatile(
        "mma.sync.aligned.m16n8k16.row.col.f32.f16.f16.f32 "
        "{%0,%1,%2,%3}, {%4,%5,%6,%7}, {%8,%9}, {%0,%1,%2,%3};"
        : "+f"(c[0]), "+f"(c[1]), "+f"(c[2]), "+f"(c[3])
        : "r"(a0), "r"(a1), "r"(a2), "r"(a3), "r"(b0), "r"(b1));
}

// ================= HMMA GEMM: g_hh[M,128](fp16) = fp16(A[M,128]) @ fp16(W[128,128]) =================
#define SM_Ah 0
#define SM_Bh (128 * LDH)
#define SMEM_TC (2 * 128 * LDH * 2)    // 69,632 B

__global__ __launch_bounds__(256) void k_gemm_tc(const float* __restrict__ Aext,
                                                 const float* __restrict__ W, int layer) {
    extern __shared__ __half smem[];
    const float* A = layer ? g_a : Aext;
    int tid  = threadIdx.x;
    int wid  = tid >> 5;
    int lane = tid & 31;
    int row0 = blockIdx.x * 128;

    // A tile fp32 -> fp16
    #pragma unroll
    for (int it = 0; it < 8; it++) {
        int i   = tid + it * 256;
        int row = i >> 4;
        int cc  = (i & 15) * 8;
        float4 v0 = make_float4(0.f, 0.f, 0.f, 0.f), v1 = v0;
        int r = row0 + row;
        if (r < NN) {
            v0 = *(const float4*)&A[r * FDIM + cc];
            v1 = *(const float4*)&A[r * FDIM + cc + 4];
        }
        uint4 pk;
        pk.x = h2_as_u32(__floats2half2_rn(v0.x, v0.y));
        pk.y = h2_as_u32(__floats2half2_rn(v0.z, v0.w));
        pk.z = h2_as_u32(__floats2half2_rn(v1.x, v1.y));
        pk.w = h2_as_u32(__floats2half2_rn(v1.z, v1.w));
        *(uint4*)&smem[SM_Ah + row * LDH + cc] = pk;
    }
    // BT[n][k] = W[k][n]
    {
        int n  = tid & 127;
        int k0 = (tid >> 7) * 64;
        #pragma unroll 8
        for (int kk = 0; kk < 64; kk++) {
            int k = k0 + kk;
            smem[SM_Bh + n * LDH + k] = __float2half_rn(W[k * FDIM + n]);
        }
    }
    __syncthreads();

    uint32_t sbA = smem_u32(&smem[SM_Ah]);
    uint32_t sbB = smem_u32(&smem[SM_Bh]);

    int m0 = (wid >> 1) * 32;
    int n0 = (wid & 1) * 64;

    float c[2][8][4];
    #pragma unroll
    for (int mi = 0; mi < 2; mi++)
        #pragma unroll
        for (int nj = 0; nj < 8; nj++)
            #pragma unroll
            for (int q = 0; q < 4; q++) c[mi][nj][q] = 0.f;

    int a_row = lane & 15;
    int a_kof = (lane >> 4) * 8;
    int b_row = lane & 7;
    int b_kof = ((lane >> 3) & 1) * 8;

    #pragma unroll
    for (int ks = 0; ks < 8; ks++) {
        int k0 = ks * 16;
        uint32_t a[2][4];
        #pragma unroll
        for (int mi = 0; mi < 2; mi++) {
            uint32_t addr = sbA + (uint32_t)((m0 + mi * 16 + a_row) * LDH + k0 + a_kof) * 2;
            ldmx4(a[mi][0], a[mi][1], a[mi][2], a[mi][3], addr);
        }
        uint32_t b[8][2];
        #pragma unroll
        for (int nj = 0; nj < 8; nj++) {
            uint32_t addr = sbB + (uint32_t)((n0 + nj * 8 + b_row) * LDH + k0 + b_kof) * 2;
            ldmx2(b[nj][0], b[nj][1], addr);
        }
        #pragma unroll
        for (int mi = 0; mi < 2; mi++)
            #pragma unroll
            for (int nj = 0; nj < 8; nj++)
                mma16816(c[mi][nj], a[mi][0], a[mi][1], a[mi][2], a[mi][3],
                         b[nj][0], b[nj][1]);
    }

    int tr = lane >> 2;
    int tc = (lane & 3) * 2;
    #pragma unroll
    for (int mi = 0; mi < 2; mi++) {
        #pragma unroll
        for (int nj = 0; nj < 8; nj++) {
            int col = n0 + nj * 8 + tc;
            int r0g = row0 + m0 + mi * 16 + tr;
            int r1g = r0g + 8;
            if (r0g < NN)
                g_hh[r0g * (FDIM/2) + (col >> 1)] = __floats2half2_rn(c[mi][nj][0], c[mi][nj][1]);
            if (r1g < NN)
                g_hh[r1g * (FDIM/2) + (col >> 1)] = __floats2half2_rn(c[mi][nj][2], c[mi][nj][3]);
        }
    }
}

// ---------------- CSR pull-aggregation: out[i] = sum_j norm * g_hh[src] + bias ----------------
__global__ __launch_bounds__(256) void k_agg(const float* __restrict__ bias,
                                             float* __restrict__ outext, int do_relu) {
    float* out = outext ? outext : g_a;
    int gw   = (blockIdx.x * blockDim.x + threadIdx.x) >> 5;   // warp = node
    int lane = threadIdx.x & 31;
    if (gw >= NN) return;
    int p0 = g_rowptr[gw], p1 = g_rowptr[gw + 1];
    float4 acc = make_float4(0.f, 0.f, 0.f, 0.f);
    const uint2* hh = (const uint2*)g_hh;          // 8B = 4 halves; row = 32 uint2
    for (int p = p0; p < p1; p++) {
        int2  e = g_edge[p];
        int   s = e.x;
        float w = __int_as_float(e.y);
        uint2 v = hh[s * 32 + lane];
        float2 f0 = __half22float2(u32_as_h2(v.x));
        float2 f1 = __half22float2(u32_as_h2(v.y));
        acc.x += w * f0.x; acc.y += w * f0.y;
        acc.z += w * f1.x; acc.w += w * f1.y;
    }
    float4 b = *(const float4*)&bias[lane * 4];
    acc.x += b.x; acc.y += b.y; acc.z += b.z; acc.w += b.w;
    if (do_relu) {
        acc.x = fmaxf(acc.x, 0.f); acc.y = fmaxf(acc.y, 0.f);
        acc.z = fmaxf(acc.z, 0.f); acc.w = fmaxf(acc.w, 0.f);
    }
    *(float4*)&out[gw * FDIM + lane * 4] = acc;
}

// ============ HMMA head: log_softmax(X @ Wl + bl) with split-fp16 (fp32-accurate) ============
// Per CTA 128 rows. X split hi/lo, WlT split hi/lo in SMEM.
// logit = Xh*Wh + Xl*Wh + Xh*Wl (xl*wl term ~1e-7, dropped).
// 8 warps, warp tile m16 x n40 (5 n-tiles of 8); 8 K16-steps; 15 MMA/step.
#define LG_XhO 0
#define LG_XlO (128 * LDH)
#define LG_WhO (2 * 128 * LDH)
#define LG_WlO (2 * 128 * LDH + CDIM * LDH)
#define LG_BLO (2 * 128 * LDH + 2 * CDIM * LDH)      // half-index where bias floats start
#define SMEM_LG (LG_BLO * 2 + CDIM * 4)              // 91,392 + 160 = 91,552 B

__global__ __launch_bounds__(256) void k_logits_tc(const float* __restrict__ X,
                                                   const float* __restrict__ Wl,
                                                   const float* __restrict__ bl,
                                                   float* __restrict__ out) {
    extern __shared__ __half smem[];
    float* sbl = (float*)&smem[LG_BLO];
    int tid  = threadIdx.x;
    int wid  = tid >> 5;
    int lane = tid & 31;
    int row0 = blockIdx.x * 128;

    // stage X hi/lo (zero-pad rows >= NN)
    #pragma unroll
    for (int it = 0; it < 8; it++) {
        int i   = tid + it * 256;
        int row = i >> 4;
        int cc  = (i & 15) * 8;
        float v[8] = {0.f, 0.f, 0.f, 0.f, 0.f, 0.f, 0.f, 0.f};
        int r = row0 + row;
        if (r < NN) {
            *(float4*)&v[0] = *(const float4*)&X[r * FDIM + cc];
            *(float4*)&v[4] = *(const float4*)&X[r * FDIM + cc + 4];
        }
        __half hi[8], lo[8];
        #pragma unroll
        for (int q = 0; q < 8; q++) {
            hi[q] = __float2half_rn(v[q]);
            lo[q] = __float2half_rn(v[q] - __half2float(hi[q]));
        }
        *(uint4*)&smem[LG_XhO + row * LDH + cc] = *(uint4*)hi;
        *(uint4*)&smem[LG_XlO + row * LDH + cc] = *(uint4*)lo;
    }
    // stage WlT hi/lo: WT[n][k] = Wl[k*CDIM + n]
    for (int idx = tid; idx < CDIM * FDIM; idx += 256) {
        int n = idx >> 7;          // 0..39
        int k = idx & 127;
        float f = Wl[k * CDIM + n];
        __half h = __float2half_rn(f);
        smem[LG_WhO + n * LDH + k] = h;
        smem[LG_WlO + n * LDH + k] = __float2half_rn(f - __half2float(h));
    }
    if (tid < CDIM) sbl[tid] = bl[tid];
    __syncthreads();

    uint32_t sbXh = smem_u32(&smem[LG_XhO]);
    uint32_t sbXl = smem_u32(&smem[LG_XlO]);
    uint32_t sbWh = smem_u32(&smem[LG_WhO]);
    uint32_t sbWl = smem_u32(&smem[LG_WlO]);

    int m0 = wid * 16;
    float c[5][4];
    #pragma unroll
    for (int nj = 0; nj < 5; nj++)
        #pragma unroll
        for (int q = 0; q < 4; q++) c[nj][q] = 0.f;

    int a_row = lane & 15;
    int a_kof = (lane >> 4) * 8;
    int b_row = lane & 7;
    int b_kof = ((lane >> 3) & 1) * 8;

    #pragma unroll
    for (int ks = 0; ks < 8; ks++) {
        int k0 = ks * 16;
        uint32_t ah[4], al[4];
        uint32_t aaddr = (uint32_t)((m0 + a_row) * LDH + k0 + a_kof) * 2;
        ldmx4(ah[0], ah[1], ah[2], ah[3], sbXh + aaddr);
        ldmx4(al[0], al[1], al[2], al[3], sbXl + aaddr);
        #pragma unroll
        for (int nj = 0; nj < 5; nj++) {
            uint32_t baddr = (uint32_t)((nj * 8 + b_row) * LDH + k0 + b_kof) * 2;
            uint32_t bh0, bh1, bl0, bl1;
            ldmx2(bh0, bh1, sbWh + baddr);
            ldmx2(bl0, bl1, sbWl + baddr);
            mma16816(c[nj], ah[0], ah[1], ah[2], ah[3], bh0, bh1);   // xh*wh
            mma16816(c[nj], al[0], al[1], al[2], al[3], bh0, bh1);   // xl*wh
            mma16816(c[nj], ah[0], ah[1], ah[2], ah[3], bl0, bl1);   // xh*wl
        }
    }

    // add bias
    int tr  = lane >> 2;
    int tc2 = (lane & 3) * 2;
    #pragma unroll
    for (int nj = 0; nj < 5; nj++) {
        float b0 = sbl[nj * 8 + tc2], b1 = sbl[nj * 8 + tc2 + 1];
        c[nj][0] += b0; c[nj][1] += b1;
        c[nj][2] += b0; c[nj][3] += b1;
    }

    // log_softmax per row; row A (m0+tr) uses c[.][0..1], row B (m0+tr+8) uses c[.][2..3].
    // Each row is held by the 4 lanes {tr*4 .. tr*4+3}: shfl_xor 1,2 reduce within group.
    float mA = -INFINITY, mB = -INFINITY;
    #pragma unroll
    for (int nj = 0; nj < 5; nj++) {
        mA = fmaxf(mA, fmaxf(c[nj][0], c[nj][1]));
        mB = fmaxf(mB, fmaxf(c[nj][2], c[nj][3]));
    }
    mA = fmaxf(mA, __shfl_xor_sync(0xffffffffu, mA, 1));
    mA = fmaxf(mA, __shfl_xor_sync(0xffffffffu, mA, 2));
    mB = fmaxf(mB, __shfl_xor_sync(0xffffffffu, mB, 1));
    mB = fmaxf(mB, __shfl_xor_sync(0xffffffffu, mB, 2));
    float sA = 0.f, sB = 0.f;
    #pragma unroll
    for (int nj = 0; nj < 5; nj++) {
        sA += expf(c[nj][0] - mA) + expf(c[nj][1] - mA);
        sB += expf(c[nj][2] - mB) + expf(c[nj][3] - mB);
    }
    sA += __shfl_xor_sync(0xffffffffu, sA, 1);
    sA += __shfl_xor_sync(0xffffffffu, sA, 2);
    sB += __shfl_xor_sync(0xffffffffu, sB, 1);
    sB += __shfl_xor_sync(0xffffffffu, sB, 2);
    float dA = mA + logf(sA), dB = mB + logf(sB);

    int rA = row0 + m0 + tr;
    int rB = rA + 8;
    #pragma unroll
    for (int nj = 0; nj < 5; nj++) {
        int col = nj * 8 + tc2;
        if (rA < NN) {
            float2 o = make_float2(c[nj][0] - dA, c[nj][1] - dA);
            *(float2*)&out[rA * CDIM + col] = o;
        }
        if (rB < NN) {
            float2 o = make_float2(c[nj][2] - dB, c[nj][3] - dB);
            *(float2*)&out[rB * CDIM + col] = o;
        }
    }
}

// ---------------- launcher (kernel launches ONLY — graph-capture safe) ----------------
extern "C" void kernel_launch(void* const* d_in, const int* in_sizes, int n_in,
                              void* d_out, int out_size) {
    const float* x  = (const float*)d_in[0];
    const int*   ei = (const int*)d_in[1];     // JAX int64 request silently yields int32
    const float* W1 = (const float*)d_in[2];
    const float* b1 = (const float*)d_in[3];
    const float* W2 = (const float*)d_in[4];
    const float* b2 = (const float*)d_in[5];
    const float* Wl = (const float*)d_in[6];
    const float* bl = (const float*)d_in[7];
    float* out  = (float*)d_out;
    float* xemb = out + (size_t)NN * CDIM;     // second output lives after logits

    cudaFuncSetAttribute(k_gemm_tc,   cudaFuncAttributeMaxDynamicSharedMemorySize, SMEM_TC);
    cudaFuncSetAttribute(k_logits_tc, cudaFuncAttributeMaxDynamicSharedMemorySize, SMEM_LG);

    // graph preprocessing
    k_zero <<<(NN + 255) / 256, 256>>>();
    k_hist <<<(NE + 255) / 256, 256>>>(ei);
    k_scan1<<<NSCB, 1024>>>();
    k_scan3<<<NSCB, 1024>>>();
    k_fill <<<(NET + 255) / 256, 256>>>(ei);

    int agg_blocks = (NN * 32 + 255) / 256;

    // layer 1: g_hh = fp16(x @ W1) ; g_a = relu(agg(g_hh) + b1)
    k_gemm_tc<<<GT_BLOCKS, 256, SMEM_TC>>>(x, W1, 0);
    k_agg<<<agg_blocks, 256>>>(b1, nullptr, 1);

    // layer 2: g_hh = fp16(g_a @ W2) ; x_emb = agg(g_hh) + b2
    k_gemm_tc<<<GT_BLOCKS, 256, SMEM_TC>>>(nullptr, W2, 1);
    k_agg<<<agg_blocks, 256>>>(b2, xemb, 0);

    // head: log_softmax(x_emb @ Wl + bl) via split-fp16 HMMA
    k_logits_tc<<<GT_BLOCKS, 256, SMEM_LG>>>(xemb, Wl, bl, out);
}

// round 14
// speedup vs baseline: 2.7427x; 1.0956x over previous
#include <cuda_runtime.h>
#include <cuda_fp16.h>
#include <math.h>
#include <stdint.h>

#define NN   50000
#define FDIM 128
#define CDIM 40
#define NE   600000
#define NET  (NE + NN)
#define NSCB 49               // ceil(NN/1024) scan blocks

// bit-casts (no standard intrinsics exist for half2<->uint)
static __device__ __forceinline__ unsigned int h2_as_u32(__half2 h) {
    return *reinterpret_cast<unsigned int*>(&h);
}
static __device__ __forceinline__ __half2 u32_as_h2(unsigned int u) {
    return *reinterpret_cast<__half2*>(&u);
}

// ---------------- device scratch (no allocations allowed) ----------------
__device__ int     g_deg[NN];           // zero at load (BSS); re-zeroed by k_scan3 each call
__device__ float   g_dinv[NN];
__device__ int     g_rowptr[NN + 1];
__device__ int     g_fill[NN];
__device__ int     g_bsum[64];
__device__ int2    g_edge[NET];         // (src, norm-bits) packed
__device__ __half2 g_hh[NN * (FDIM/2)]; // GEMM output in fp16 (gather-traffic halved)
__device__ float   g_a[NN * FDIM];      // aggregated buffer (layer-1 activations)

// ---------------- graph preprocessing ----------------
__global__ void k_hist(const int* __restrict__ ei) {
    int e = blockIdx.x * blockDim.x + threadIdx.x;
    if (e < NE) atomicAdd(&g_deg[ei[NE + e]], 1);
}

// phase 1: per-block (1024-wide) exclusive scan of (deg+1); also dinv
__global__ __launch_bounds__(1024) void k_scan1() {
    __shared__ int warp_sums[32];
    int tid  = threadIdx.x;
    int lane = tid & 31;
    int wid  = tid >> 5;
    int i = blockIdx.x * 1024 + tid;
    int v = 0;
    if (i < NN) {
        v = g_deg[i] + 1;                       // +1 self loop
        g_dinv[i] = rsqrtf((float)v);
    }
    int x = v;
    #pragma unroll
    for (int o = 1; o < 32; o <<= 1) {
        int y = __shfl_up_sync(0xffffffffu, x, o);
        if (lane >= o) x += y;
    }
    if (lane == 31) warp_sums[wid] = x;
    __syncthreads();
    if (wid == 0) {
        int ws = warp_sums[lane];
        #pragma unroll
        for (int o = 1; o < 32; o <<= 1) {
            int y = __shfl_up_sync(0xffffffffu, ws, o);
            if (lane >= o) ws += y;
        }
        warp_sums[lane] = ws;
    }
    __syncthreads();
    int excl = (wid ? warp_sums[wid - 1] : 0) + x - v;
    if (i < NN) g_rowptr[i] = excl;
    if (tid == 1023) g_bsum[blockIdx.x] = excl + v;
}

// phase 2+3 fused: block-offset add, zero fill counters, AND re-zero g_deg for
// the next invocation (g_deg was already consumed by k_scan1 this invocation).
__global__ __launch_bounds__(1024) void k_scan3() {
    __shared__ int s_off;
    int b = blockIdx.x;
    if (threadIdx.x < 32) {
        int lane = threadIdx.x;
        int acc = 0;
        for (int idx = lane; idx < b; idx += 32) acc += g_bsum[idx];   // <=2 iters
        #pragma unroll
        for (int o = 16; o; o >>= 1) acc += __shfl_xor_sync(0xffffffffu, acc, o);
        if (lane == 0) s_off = acc;
    }
    __syncthreads();
    int i = b * 1024 + threadIdx.x;
    if (i < NN) {
        g_rowptr[i] += s_off;
        g_fill[i] = 0;
        g_deg[i]  = 0;          // ready for next call's k_hist
    }
    if (b == 0 && threadIdx.x == 0) g_rowptr[NN] = NET;
}

__global__ void k_fill(const int* __restrict__ ei) {
    int e = blockIdx.x * blockDim.x + threadIdx.x;
    if (e >= NET) return;
    int s, d;
    if (e < NE) { s = ei[e]; d = ei[NE + e]; }
    else        { s = d = e - NE; }                    // self loop
    int p = g_rowptr[d] + atomicAdd(&g_fill[d], 1);
    g_edge[p] = make_int2(s, __float_as_int(g_dinv[s] * g_dinv[d]));
}

// ================= shared HMMA plumbing (sm_80+ PTX; valid on compute_103) =================
#define LDH 136                        // row stride in halves (16B-aligned, conflict-free)
#define GT_BLOCKS ((NN + 127) / 128)

__device__ __forceinline__ uint32_t smem_u32(const void* p) {
    uint32_t a;
    asm("{ .reg .u64 t; cvta.to.shared.u64 t, %1; cvt.u32.u64 %0, t; }" : "=r"(a) : "l"(p));
    return a;
}
__device__ __forceinline__ void ldmx4(uint32_t& r0, uint32_t& r1, uint32_t& r2, uint32_t& r3,
                                      uint32_t addr) {
    asm volatile("ldmatrix.sync.aligned.m8n8.x4.shared.b16 {%0,%1,%2,%3}, [%4];"
                 : "=r"(r0), "=r"(r1), "=r"(r2), "=r"(r3) : "r"(addr));
}
__device__ __forceinline__ void ldmx2(uint32_t& r0, uint32_t& r1, uint32_t addr) {
    asm volatile("ldmatrix.sync.aligned.m8n8.x2.shared.b16 {%0,%1}, [%2];"
                 : "=r"(r0), "=r"(r1) : "r"(addr));
}
__device__ __forceinline__ void mma16816(float* c, uint32_t a0, uint32_t a1, uint32_t a2,
                                         uint32_t a3, uint32_t b0, uint32_t b1) {
    asm volatile(
        "mma.sync.aligned.m16n8k16.row.col.f32.f16.f16.f32 "
        "{%0,%1,%2,%3}, {%4,%5,%6,%7}, {%8,%9}, {%0,%1,%2,%3};"
        : "+f"(c[0]), "+f"(c[1]), "+f"(c[2]), "+f"(c[3])
        : "r"(a0), "r"(a1), "r"(a2), "r"(a3), "r"(b0), "r"(b1));
}

// ================= HMMA GEMM: g_hh[M,128](fp16) = fp16(A[M,128]) @ fp16(W[128,128]) =================
#define SM_Ah 0
#define SM_Bh (128 * LDH)
#define SMEM_TC (2 * 128 * LDH * 2)    // 69,632 B

__global__ __launch_bounds__(256) void k_gemm_tc(const float* __restrict__ Aext,
                                                 const float* __restrict__ W, int layer) {
    extern __shared__ __half smem[];
    const float* A = layer ? g_a : Aext;
    int tid  = threadIdx.x;
    int wid  = tid >> 5;
    int lane = tid & 31;
    int row0 = blockIdx.x * 128;

    // A tile fp32 -> fp16
    #pragma unroll
    for (int it = 0; it < 8; it++) {
        int i   = tid + it * 256;
        int row = i >> 4;
        int cc  = (i & 15) * 8;
        float4 v0 = make_float4(0.f, 0.f, 0.f, 0.f), v1 = v0;
        int r = row0 + row;
        if (r < NN) {
            v0 = *(const float4*)&A[r * FDIM + cc];
            v1 = *(const float4*)&A[r * FDIM + cc + 4];
        }
        uint4 pk;
        pk.x = h2_as_u32(__floats2half2_rn(v0.x, v0.y));
        pk.y = h2_as_u32(__floats2half2_rn(v0.z, v0.w));
        pk.z = h2_as_u32(__floats2half2_rn(v1.x, v1.y));
        pk.w = h2_as_u32(__floats2half2_rn(v1.z, v1.w));
        *(uint4*)&smem[SM_Ah + row * LDH + cc] = pk;
    }
    // BT[n][k] = W[k][n]
    {
        int n  = tid & 127;
        int k0 = (tid >> 7) * 64;
        #pragma unroll 8
        for (int kk = 0; kk < 64; kk++) {
            int k = k0 + kk;
            smem[SM_Bh + n * LDH + k] = __float2half_rn(W[k * FDIM + n]);
        }
    }
    __syncthreads();

    uint32_t sbA = smem_u32(&smem[SM_Ah]);
    uint32_t sbB = smem_u32(&smem[SM_Bh]);

    int m0 = (wid >> 1) * 32;
    int n0 = (wid & 1) * 64;

    float c[2][8][4];
    #pragma unroll
    for (int mi = 0; mi < 2; mi++)
        #pragma unroll
        for (int nj = 0; nj < 8; nj++)
            #pragma unroll
            for (int q = 0; q < 4; q++) c[mi][nj][q] = 0.f;

    int a_row = lane & 15;
    int a_kof = (lane >> 4) * 8;
    int b_row = lane & 7;
    int b_kof = ((lane >> 3) & 1) * 8;

    #pragma unroll
    for (int ks = 0; ks < 8; ks++) {
        int k0 = ks * 16;
        uint32_t a[2][4];
        #pragma unroll
        for (int mi = 0; mi < 2; mi++) {
            uint32_t addr = sbA + (uint32_t)((m0 + mi * 16 + a_row) * LDH + k0 + a_kof) * 2;
            ldmx4(a[mi][0], a[mi][1], a[mi][2], a[mi][3], addr);
        }
        uint32_t b[8][2];
        #pragma unroll
        for (int nj = 0; nj < 8; nj++) {
            uint32_t addr = sbB + (uint32_t)((n0 + nj * 8 + b_row) * LDH + k0 + b_kof) * 2;
            ldmx2(b[nj][0], b[nj][1], addr);
        }
        #pragma unroll
        for (int mi = 0; mi < 2; mi++)
            #pragma unroll
            for (int nj = 0; nj < 8; nj++)
                mma16816(c[mi][nj], a[mi][0], a[mi][1], a[mi][2], a[mi][3],
                         b[nj][0], b[nj][1]);
    }

    int tr = lane >> 2;
    int tc = (lane & 3) * 2;
    #pragma unroll
    for (int mi = 0; mi < 2; mi++) {
        #pragma unroll
        for (int nj = 0; nj < 8; nj++) {
            int col = n0 + nj * 8 + tc;
            int r0g = row0 + m0 + mi * 16 + tr;
            int r1g = r0g + 8;
            if (r0g < NN)
                g_hh[r0g * (FDIM/2) + (col >> 1)] = __floats2half2_rn(c[mi][nj][0], c[mi][nj][1]);
            if (r1g < NN)
                g_hh[r1g * (FDIM/2) + (col >> 1)] = __floats2half2_rn(c[mi][nj][2], c[mi][nj][3]);
        }
    }
}

// ---------------- CSR pull-aggregation: out[i] = sum_j norm * g_hh[src] + bias ----------------
__global__ __launch_bounds__(256) void k_agg(const float* __restrict__ bias,
                                             float* __restrict__ outext, int do_relu) {
    float* out = outext ? outext : g_a;
    int gw   = (blockIdx.x * blockDim.x + threadIdx.x) >> 5;   // warp = node
    int lane = threadIdx.x & 31;
    if (gw >= NN) return;
    int p0 = g_rowptr[gw], p1 = g_rowptr[gw + 1];
    float4 acc = make_float4(0.f, 0.f, 0.f, 0.f);
    const uint2* hh = (const uint2*)g_hh;          // 8B = 4 halves; row = 32 uint2
    for (int p = p0; p < p1; p++) {
        int2  e = g_edge[p];
        int   s = e.x;
        float w = __int_as_float(e.y);
        uint2 v = hh[s * 32 + lane];
        float2 f0 = __half22float2(u32_as_h2(v.x));
        float2 f1 = __half22float2(u32_as_h2(v.y));
        acc.x += w * f0.x; acc.y += w * f0.y;
        acc.z += w * f1.x; acc.w += w * f1.y;
    }
    float4 b = *(const float4*)&bias[lane * 4];
    acc.x += b.x; acc.y += b.y; acc.z += b.z; acc.w += b.w;
    if (do_relu) {
        acc.x = fmaxf(acc.x, 0.f); acc.y = fmaxf(acc.y, 0.f);
        acc.z = fmaxf(acc.z, 0.f); acc.w = fmaxf(acc.w, 0.f);
    }
    *(float4*)&out[gw * FDIM + lane * 4] = acc;
}

// ============ HMMA head: log_softmax(X @ Wl + bl) with split-fp16 (fp32-accurate) ============
#define LG_XhO 0
#define LG_XlO (128 * LDH)
#define LG_WhO (2 * 128 * LDH)
#define LG_WlO (2 * 128 * LDH + CDIM * LDH)
#define LG_BLO (2 * 128 * LDH + 2 * CDIM * LDH)      // half-index where bias floats start
#define SMEM_LG (LG_BLO * 2 + CDIM * 4)

__global__ __launch_bounds__(256) void k_logits_tc(const float* __restrict__ X,
                                                   const float* __restrict__ Wl,
                                                   const float* __restrict__ bl,
                                                   float* __restrict__ out) {
    extern __shared__ __half smem[];
    float* sbl = (float*)&smem[LG_BLO];
    int tid  = threadIdx.x;
    int wid  = tid >> 5;
    int lane = tid & 31;
    int row0 = blockIdx.x * 128;

    #pragma unroll
    for (int it = 0; it < 8; it++) {
        int i   = tid + it * 256;
        int row = i >> 4;
        int cc  = (i & 15) * 8;
        float v[8] = {0.f, 0.f, 0.f, 0.f, 0.f, 0.f, 0.f, 0.f};
        int r = row0 + row;
        if (r < NN) {
            *(float4*)&v[0] = *(const float4*)&X[r * FDIM + cc];
            *(float4*)&v[4] = *(const float4*)&X[r * FDIM + cc + 4];
        }
        __half hi[8], lo[8];
        #pragma unroll
        for (int q = 0; q < 8; q++) {
            hi[q] = __float2half_rn(v[q]);
            lo[q] = __float2half_rn(v[q] - __half2float(hi[q]));
        }
        *(uint4*)&smem[LG_XhO + row * LDH + cc] = *(uint4*)hi;
        *(uint4*)&smem[LG_XlO + row * LDH + cc] = *(uint4*)lo;
    }
    for (int idx = tid; idx < CDIM * FDIM; idx += 256) {
        int n = idx >> 7;
        int k = idx & 127;
        float f = Wl[k * CDIM + n];
        __half h = __float2half_rn(f);
        smem[LG_WhO + n * LDH + k] = h;
        smem[LG_WlO + n * LDH + k] = __float2half_rn(f - __half2float(h));
    }
    if (tid < CDIM) sbl[tid] = bl[tid];
    __syncthreads();

    uint32_t sbXh = smem_u32(&smem[LG_XhO]);
    uint32_t sbXl = smem_u32(&smem[LG_XlO]);
    uint32_t sbWh = smem_u32(&smem[LG_WhO]);
    uint32_t sbWl = smem_u32(&smem[LG_WlO]);

    int m0 = wid * 16;
    float c[5][4];
    #pragma unroll
    for (int nj = 0; nj < 5; nj++)
        #pragma unroll
        for (int q = 0; q < 4; q++) c[nj][q] = 0.f;

    int a_row = lane & 15;
    int a_kof = (lane >> 4) * 8;
    int b_row = lane & 7;
    int b_kof = ((lane >> 3) & 1) * 8;

    #pragma unroll
    for (int ks = 0; ks < 8; ks++) {
        int k0 = ks * 16;
        uint32_t ah[4], al[4];
        uint32_t aaddr = (uint32_t)((m0 + a_row) * LDH + k0 + a_kof) * 2;
        ldmx4(ah[0], ah[1], ah[2], ah[3], sbXh + aaddr);
        ldmx4(al[0], al[1], al[2], al[3], sbXl + aaddr);
        #pragma unroll
        for (int nj = 0; nj < 5; nj++) {
            uint32_t baddr = (uint32_t)((nj * 8 + b_row) * LDH + k0 + b_kof) * 2;
            uint32_t bh0, bh1, bl0, bl1;
            ldmx2(bh0, bh1, sbWh + baddr);
            ldmx2(bl0, bl1, sbWl + baddr);
            mma16816(c[nj], ah[0], ah[1], ah[2], ah[3], bh0, bh1);   // xh*wh
            mma16816(c[nj], al[0], al[1], al[2], al[3], bh0, bh1);   // xl*wh
            mma16816(c[nj], ah[0], ah[1], ah[2], ah[3], bl0, bl1);   // xh*wl
        }
    }

    int tr  = lane >> 2;
    int tc2 = (lane & 3) * 2;
    #pragma unroll
    for (int nj = 0; nj < 5; nj++) {
        float b0 = sbl[nj * 8 + tc2], b1 = sbl[nj * 8 + tc2 + 1];
        c[nj][0] += b0; c[nj][1] += b1;
        c[nj][2] += b0; c[nj][3] += b1;
    }

    float mA = -INFINITY, mB = -INFINITY;
    #pragma unroll
    for (int nj = 0; nj < 5; nj++) {
        mA = fmaxf(mA, fmaxf(c[nj][0], c[nj][1]));
        mB = fmaxf(mB, fmaxf(c[nj][2], c[nj][3]));
    }
    mA = fmaxf(mA, __shfl_xor_sync(0xffffffffu, mA, 1));
    mA = fmaxf(mA, __shfl_xor_sync(0xffffffffu, mA, 2));
    mB = fmaxf(mB, __shfl_xor_sync(0xffffffffu, mB, 1));
    mB = fmaxf(mB, __shfl_xor_sync(0xffffffffu, mB, 2));
    float sA = 0.f, sB = 0.f;
    #pragma unroll
    for (int nj = 0; nj < 5; nj++) {
        sA += expf(c[nj][0] - mA) + expf(c[nj][1] - mA);
        sB += expf(c[nj][2] - mB) + expf(c[nj][3] - mB);
    }
    sA += __shfl_xor_sync(0xffffffffu, sA, 1);
    sA += __shfl_xor_sync(0xffffffffu, sA, 2);
    sB += __shfl_xor_sync(0xffffffffu, sB, 1);
    sB += __shfl_xor_sync(0xffffffffu, sB, 2);
    float dA = mA + logf(sA), dB = mB + logf(sB);

    int rA = row0 + m0 + tr;
    int rB = rA + 8;
    #pragma unroll
    for (int nj = 0; nj < 5; nj++) {
        int col = nj * 8 + tc2;
        if (rA < NN) {
            float2 o = make_float2(c[nj][0] - dA, c[nj][1] - dA);
            *(float2*)&out[rA * CDIM + col] = o;
        }
        if (rB < NN) {
            float2 o = make_float2(c[nj][2] - dB, c[nj][3] - dB);
            *(float2*)&out[rB * CDIM + col] = o;
        }
    }
}

// ---------------- launcher (graph-capture safe; fork gemm1 beside preproc) ----------------
extern "C" void kernel_launch(void* const* d_in, const int* in_sizes, int n_in,
                              void* d_out, int out_size) {
    const float* x  = (const float*)d_in[0];
    const int*   ei = (const int*)d_in[1];     // JAX int64 request silently yields int32
    const float* W1 = (const float*)d_in[2];
    const float* b1 = (const float*)d_in[3];
    const float* W2 = (const float*)d_in[4];
    const float* b2 = (const float*)d_in[5];
    const float* Wl = (const float*)d_in[6];
    const float* bl = (const float*)d_in[7];
    float* out  = (float*)d_out;
    float* xemb = out + (size_t)NN * CDIM;     // second output lives after logits

    cudaFuncSetAttribute(k_gemm_tc,   cudaFuncAttributeMaxDynamicSharedMemorySize, SMEM_TC);
    cudaFuncSetAttribute(k_logits_tc, cudaFuncAttributeMaxDynamicSharedMemorySize, SMEM_LG);

    // fork: gemm1 depends only on (x, W1) — run it beside the preproc chain.
    // Stream/events created per call (host-side, not captured, no device mem);
    // intentionally not destroyed (kernel_launch is invoked only a few times;
    // destroying capture-participating handles mid-capture is unsafe).
    cudaStream_t s2;
    cudaEvent_t  evFork, evJoin;
    cudaStreamCreateWithFlags(&s2, cudaStreamNonBlocking);
    cudaEventCreateWithFlags(&evFork, cudaEventDisableTiming);
    cudaEventCreateWithFlags(&evJoin, cudaEventDisableTiming);

    cudaEventRecord(evFork, 0);
    cudaStreamWaitEvent(s2, evFork, 0);
    k_gemm_tc<<<GT_BLOCKS, 256, SMEM_TC, s2>>>(x, W1, 0);   // layer-1 GEMM on side branch
    cudaEventRecord(evJoin, s2);

    // preprocessing chain on the main (capture) stream
    // (g_deg arrives zeroed: BSS init on first call, k_scan3 re-zeroes thereafter)
    k_hist <<<(NE + 255) / 256, 256>>>(ei);
    k_scan1<<<NSCB, 1024>>>();
    k_scan3<<<NSCB, 1024>>>();
    k_fill <<<(NET + 255) / 256, 256>>>(ei);

    cudaStreamWaitEvent(0, evJoin, 0);   // join: agg1 needs both fill and gemm1

    int agg_blocks = (NN * 32 + 255) / 256;

    // layer 1 aggregation: g_a = relu(agg(g_hh) + b1)
    k_agg<<<agg_blocks, 256>>>(b1, nullptr, 1);

    // layer 2: g_hh = fp16(g_a @ W2) ; x_emb = agg(g_hh) + b2
    k_gemm_tc<<<GT_BLOCKS, 256, SMEM_TC>>>(nullptr, W2, 1);
    k_agg<<<agg_blocks, 256>>>(b2, xemb, 0);

    // head: log_softmax(x_emb @ Wl + bl) via split-fp16 HMMA
    k_logits_tc<<<GT_BLOCKS, 256, SMEM_LG>>>(xemb, Wl, bl, out);
}